// round 16
// baseline (speedup 1.0000x reference)
#include <cuda_runtime.h>
#include <cuda_fp16.h>
#include <cstdint>

#define N_DIM 2048
#define H_DIM 2048
#define V_DIM 32000

// ---- scratch ----
__device__ __half g_Wh[(size_t)V_DIM * H_DIM];   // 131 MB
__device__ __half g_xh[(size_t)N_DIM * H_DIM];   // 8 MB
__device__ double g_acc;
__device__ unsigned g_count = 0;

// ============================================================
// Kernel 1: fp32 -> fp16 conversion; zero accumulator
//   W path: 8 floats/iter, 16B stores
// ============================================================
__global__ void convert_kernel(const float* __restrict__ x,
                               const float* __restrict__ W) {
    size_t tid = (size_t)blockIdx.x * blockDim.x + threadIdx.x;
    size_t stride = (size_t)gridDim.x * blockDim.x;
    if (tid == 0) g_acc = 0.0;

    const size_t nW8 = (size_t)V_DIM * H_DIM / 8;
    const float4* W4 = (const float4*)W;
    for (size_t i = tid; i < nW8; i += stride) {
        float4 v0 = W4[2 * i];
        float4 v1 = W4[2 * i + 1];
        __half2 h0 = __floats2half2_rn(v0.x, v0.y);
        __half2 h1 = __floats2half2_rn(v0.z, v0.w);
        __half2 h2 = __floats2half2_rn(v1.x, v1.y);
        __half2 h3 = __floats2half2_rn(v1.z, v1.w);
        uint4 pack;
        pack.x = *(uint32_t*)&h0; pack.y = *(uint32_t*)&h1;
        pack.z = *(uint32_t*)&h2; pack.w = *(uint32_t*)&h3;
        ((uint4*)g_Wh)[i] = pack;
    }
    const size_t nx8 = (size_t)N_DIM * H_DIM / 8;
    const float4* x4 = (const float4*)x;
    for (size_t i = tid; i < nx8; i += stride) {
        float4 v0 = x4[2 * i];
        float4 v1 = x4[2 * i + 1];
        __half2 h0 = __floats2half2_rn(v0.x, v0.y);
        __half2 h1 = __floats2half2_rn(v0.z, v0.w);
        __half2 h2 = __floats2half2_rn(v1.x, v1.y);
        __half2 h3 = __floats2half2_rn(v1.z, v1.w);
        uint4 pack;
        pack.x = *(uint32_t*)&h0; pack.y = *(uint32_t*)&h1;
        pack.z = *(uint32_t*)&h2; pack.w = *(uint32_t*)&h3;
        ((uint4*)g_xh)[i] = pack;
    }
}

// ============================================================
// Kernel 2: fp16 HMMA GEMM (f16 acc), 2 CTAs/SM, fat warp tiles
//   CTA tile 128x256, BK=64; 8 warps (2 M x 4 N), warp tile 64x64
//   Hoisted swizzle addressing: addr = base_mi + ((ks<<5) ^ xbase)
//   2-stage cp.async; fused MSE reduce + last-CTA finalize
// ============================================================
#define BM 128
#define BN 256
#define BK 64
#define NK (H_DIM / BK)               // 32
#define A_BYTES (BM * BK * 2)         // 16384
#define B_BYTES (BN * BK * 2)         // 32768
#define STAGE_BYTES (A_BYTES + B_BYTES)    // 49152
#define SMEM_BYTES (2 * STAGE_BYTES)       // 98304 -> 2 CTAs = 192KB
#define THREADS 256
#define NUM_CTAS ((N_DIM / BM) * (V_DIM / BN))   // 2000

__device__ __forceinline__ void cp_async16(uint32_t smem_addr, const void* gptr) {
    asm volatile("cp.async.cg.shared.global [%0], [%1], 16;"
                 :: "r"(smem_addr), "l"(gptr));
}

__global__ void __launch_bounds__(THREADS, 2)
gemm_mse_kernel(const float* __restrict__ y, float* __restrict__ out) {
    extern __shared__ __align__(1024) char smem[];
    __shared__ float red[8];

    const int tid = threadIdx.x;
    const int lane = tid & 31;
    const int warp = tid >> 5;
    const int warp_m = warp & 1;   // 0..1 -> 64-row slabs (M)
    const int warp_n = warp >> 1;  // 0..3 -> 64-col slabs (N)

    const uint32_t sbase = (uint32_t)__cvta_generic_to_shared(smem);

    const int n_blk = blockIdx.x * BM;
    const int v_blk = blockIdx.y * BN;
    const __half* gA = g_xh + (size_t)n_blk * H_DIM;
    const __half* gB = g_Wh + (size_t)v_blk * H_DIM;

    // loader: A 1024 chunks (4/thread), B 2048 chunks (8/thread)
    auto issue_tile = [&](int kt) {
        const uint32_t st = sbase + (kt & 1) * STAGE_BYTES;
        const __half* gAk = gA + kt * BK;
        const __half* gBk = gB + kt * BK;
        #pragma unroll
        for (int i = 0; i < 4; i++) {
            int chunk = i * THREADS + tid;   // 0..1023
            int row = chunk >> 3;            // 0..127
            int c16 = chunk & 7;
            uint32_t off = (uint32_t)(row * 128 + ((c16 ^ (row & 7)) * 16));
            cp_async16(st + off, gAk + (size_t)row * H_DIM + c16 * 8);
        }
        #pragma unroll
        for (int i = 0; i < 8; i++) {
            int chunk = i * THREADS + tid;   // 0..2047
            int row = chunk >> 3;            // 0..255
            int c16 = chunk & 7;
            uint32_t off = (uint32_t)(row * 128 + ((c16 ^ (row & 7)) * 16));
            cp_async16(st + A_BYTES + off, gBk + (size_t)row * H_DIM + c16 * 8);
        }
        asm volatile("cp.async.commit_group;");
    };

    issue_tile(0);

    // f16x2 accumulators: warp tile 64x64 -> 4 mi x 8 ni x 2 regs = 64 regs
    uint32_t c[4][8][2];
    #pragma unroll
    for (int mi = 0; mi < 4; mi++)
        #pragma unroll
        for (int ni = 0; ni < 8; ni++) { c[mi][ni][0] = 0u; c[mi][ni][1] = 0u; }

    // ---- hoisted fragment addressing ----
    // addr(mi, ks) = stageBase + off[mi] + ((ks<<5) ^ xbase)
    //   off  = row*128 + ((kl ^ (r7&1)) << 4)
    //   xbase = (r7&6) << 4       (r7 = row&7, same for all mi/p slabs)
    const int a_row = warp_m * 64 + (lane & 15);
    const int a_r7 = a_row & 7;
    const int a_kl = lane >> 4;
    uint32_t a_off[4];
    #pragma unroll
    for (int mi = 0; mi < 4; mi++)
        a_off[mi] = (uint32_t)((a_row + mi * 16) * 128 + ((a_kl ^ (a_r7 & 1)) << 4));
    const uint32_t a_xb = (uint32_t)((a_r7 & 6) << 4);

    const int b_row = warp_n * 64 + (lane & 7) + ((lane >> 4) << 3);
    const int b_r7 = b_row & 7;
    const int b_kl = (lane >> 3) & 1;
    uint32_t b_off[4];
    #pragma unroll
    for (int p = 0; p < 4; p++)
        b_off[p] = (uint32_t)(A_BYTES + (b_row + p * 16) * 128 + ((b_kl ^ (b_r7 & 1)) << 4));
    const uint32_t b_xb = (uint32_t)((b_r7 & 6) << 4);

    for (int kt = 0; kt < NK; kt++) {
        asm volatile("cp.async.wait_group 0;");
        __syncthreads();
        if (kt + 1 < NK) issue_tile(kt + 1);   // overlaps compute of kt

        const uint32_t stBase = sbase + (kt & 1) * STAGE_BYTES;

        #pragma unroll
        for (int ks = 0; ks < 4; ks++) {   // 4 x k16 per tile
            const uint32_t axr = ((uint32_t)(ks << 5)) ^ a_xb;
            const uint32_t bxr = ((uint32_t)(ks << 5)) ^ b_xb;
            uint32_t a[4][4];
            #pragma unroll
            for (int mi = 0; mi < 4; mi++) {
                uint32_t addr = stBase + a_off[mi] + axr;
                asm volatile(
                    "ldmatrix.sync.aligned.m8n8.x4.shared.b16 {%0,%1,%2,%3}, [%4];"
                    : "=r"(a[mi][0]), "=r"(a[mi][1]), "=r"(a[mi][2]), "=r"(a[mi][3])
                    : "r"(addr));
            }
            uint32_t b[4][4];
            #pragma unroll
            for (int p = 0; p < 4; p++) {
                uint32_t addr = stBase + b_off[p] + bxr;
                asm volatile(
                    "ldmatrix.sync.aligned.m8n8.x4.shared.b16 {%0,%1,%2,%3}, [%4];"
                    : "=r"(b[p][0]), "=r"(b[p][1]), "=r"(b[p][2]), "=r"(b[p][3])
                    : "r"(addr));
            }
            #pragma unroll
            for (int mi = 0; mi < 4; mi++) {
                #pragma unroll
                for (int ni = 0; ni < 8; ni++) {
                    int p = ni >> 1;
                    int o = (ni & 1) * 2;
                    asm volatile(
                        "mma.sync.aligned.m16n8k16.row.col.f16.f16.f16.f16 "
                        "{%0,%1}, {%2,%3,%4,%5}, {%6,%7}, {%0,%1};"
                        : "+r"(c[mi][ni][0]), "+r"(c[mi][ni][1])
                        : "r"(a[mi][0]), "r"(a[mi][1]), "r"(a[mi][2]), "r"(a[mi][3]),
                          "r"(b[p][o]), "r"(b[p][o + 1]));
                }
            }
        }
    }

    // ---- epilogue: (logit - y)^2 ----
    const int gr = lane >> 2;
    const int gc = (lane & 3) * 2;
    float acc = 0.0f;
    #pragma unroll
    for (int mi = 0; mi < 4; mi++) {
        int gn0 = n_blk + warp_m * 64 + mi * 16 + gr;
        const float* y0 = y + (size_t)gn0 * V_DIM + v_blk;
        const float* y8 = y0 + (size_t)8 * V_DIM;
        #pragma unroll
        for (int ni = 0; ni < 8; ni++) {
            int col = warp_n * 64 + ni * 8 + gc;
            float2 y01 = *(const float2*)(y0 + col);
            float2 y23 = *(const float2*)(y8 + col);
            float2 c01 = __half22float2(*(__half2*)&c[mi][ni][0]);
            float2 c23 = __half22float2(*(__half2*)&c[mi][ni][1]);
            float d0 = c01.x - y01.x;
            float d1 = c01.y - y01.y;
            float d2 = c23.x - y23.x;
            float d3 = c23.y - y23.y;
            acc += d0 * d0 + d1 * d1 + d2 * d2 + d3 * d3;
        }
    }
    #pragma unroll
    for (int off = 16; off; off >>= 1)
        acc += __shfl_xor_sync(0xFFFFFFFFu, acc, off);
    if (lane == 0) red[warp] = acc;
    __syncthreads();
    if (warp == 0) {
        float sv = (lane < 8) ? red[lane] : 0.0f;
        #pragma unroll
        for (int off = 4; off; off >>= 1)
            sv += __shfl_xor_sync(0xFFFFFFFFu, sv, off);
        if (lane == 0) {
            atomicAdd(&g_acc, (double)sv);
            __threadfence();
            unsigned done = atomicAdd(&g_count, 1u);
            if (done == NUM_CTAS - 1) {
                double total = atomicAdd(&g_acc, 0.0);   // ordered read
                out[0] = (float)(total / ((double)N_DIM * (double)V_DIM));
                g_count = 0;   // reset for next graph replay
            }
        }
    }
}

// ============================================================
extern "C" void kernel_launch(void* const* d_in, const int* in_sizes, int n_in,
                              void* d_out, int out_size) {
    (void)in_sizes; (void)n_in; (void)out_size;
    const float* x = (const float*)d_in[0];   // [N, H]
    const float* y = (const float*)d_in[1];   // [N, V]
    const float* W = (const float*)d_in[2];   // [V, H]
    float* out = (float*)d_out;

    static bool attr_set = false;
    if (!attr_set) {
        cudaFuncSetAttribute(gemm_mse_kernel,
                             cudaFuncAttributeMaxDynamicSharedMemorySize,
                             SMEM_BYTES);
        attr_set = true;
    }

    convert_kernel<<<2048, 256>>>(x, W);

    dim3 grid(N_DIM / BM, V_DIM / BN);  // (16, 125): x-fastest -> W stripe L2 reuse
    gemm_mse_kernel<<<grid, THREADS, SMEM_BYTES>>>(y, out);
}

// round 17
// speedup vs baseline: 1.4956x; 1.4956x over previous
#include <cuda_runtime.h>
#include <cuda_fp16.h>
#include <cstdint>

#define N_DIM 2048
#define H_DIM 2048
#define V_DIM 32000

// ---- scratch ----
__device__ __half g_Wh[(size_t)V_DIM * H_DIM];   // 131 MB
__device__ __half g_xh[(size_t)N_DIM * H_DIM];   // 8 MB
__device__ double g_acc;
__device__ unsigned g_count = 0;

// ============================================================
// Kernel 1: fp32 -> fp16 conversion; zero accumulator
//   (round-14 coalesced form: thread-contiguous float4 reads)
// ============================================================
__global__ void convert_kernel(const float* __restrict__ x,
                               const float* __restrict__ W) {
    size_t tid = (size_t)blockIdx.x * blockDim.x + threadIdx.x;
    size_t stride = (size_t)gridDim.x * blockDim.x;
    if (tid == 0) g_acc = 0.0;

    const size_t nW4 = (size_t)V_DIM * H_DIM / 4;
    const float4* W4 = (const float4*)W;
    for (size_t i = tid; i < nW4; i += stride) {
        float4 v = W4[i];
        __half2* dst = (__half2*)(g_Wh + i * 4);
        dst[0] = __floats2half2_rn(v.x, v.y);
        dst[1] = __floats2half2_rn(v.z, v.w);
    }
    const size_t nx4 = (size_t)N_DIM * H_DIM / 4;
    const float4* x4 = (const float4*)x;
    for (size_t i = tid; i < nx4; i += stride) {
        float4 v = x4[i];
        __half2* dst = (__half2*)(g_xh + i * 4);
        dst[0] = __floats2half2_rn(v.x, v.y);
        dst[1] = __floats2half2_rn(v.z, v.w);
    }
}

// ============================================================
// Kernel 2: fp16 HMMA GEMM (f16 acc), 2 CTAs/SM, fat warp tiles
//   CTA tile 128x256, BK=64; 8 warps (2 M x 4 N), warp tile 64x64
//   Hoisted swizzle addressing: addr = stageBase + off[] + ((ks<<5) ^ xbase)
//   2-stage cp.async; fused MSE reduce + last-CTA finalize
// ============================================================
#define BM 128
#define BN 256
#define BK 64
#define NK (H_DIM / BK)               // 32
#define A_BYTES (BM * BK * 2)         // 16384
#define B_BYTES (BN * BK * 2)         // 32768
#define STAGE_BYTES (A_BYTES + B_BYTES)    // 49152
#define SMEM_BYTES (2 * STAGE_BYTES)       // 98304 -> 2 CTAs = 192KB
#define THREADS 256
#define NUM_CTAS ((N_DIM / BM) * (V_DIM / BN))   // 2000

__device__ __forceinline__ void cp_async16(uint32_t smem_addr, const void* gptr) {
    asm volatile("cp.async.cg.shared.global [%0], [%1], 16;"
                 :: "r"(smem_addr), "l"(gptr));
}

__global__ void __launch_bounds__(THREADS, 2)
gemm_mse_kernel(const float* __restrict__ y, float* __restrict__ out) {
    extern __shared__ __align__(1024) char smem[];
    __shared__ float red[8];

    const int tid = threadIdx.x;
    const int lane = tid & 31;
    const int warp = tid >> 5;
    const int warp_m = warp & 1;   // 0..1 -> 64-row slabs (M)
    const int warp_n = warp >> 1;  // 0..3 -> 64-col slabs (N)

    const uint32_t sbase = (uint32_t)__cvta_generic_to_shared(smem);

    const int n_blk = blockIdx.x * BM;
    const int v_blk = blockIdx.y * BN;
    const __half* gA = g_xh + (size_t)n_blk * H_DIM;
    const __half* gB = g_Wh + (size_t)v_blk * H_DIM;

    // loader: A 1024 chunks (4/thread), B 2048 chunks (8/thread)
    auto issue_tile = [&](int kt) {
        const uint32_t st = sbase + (kt & 1) * STAGE_BYTES;
        const __half* gAk = gA + kt * BK;
        const __half* gBk = gB + kt * BK;
        #pragma unroll
        for (int i = 0; i < 4; i++) {
            int chunk = i * THREADS + tid;   // 0..1023
            int row = chunk >> 3;            // 0..127
            int c16 = chunk & 7;
            uint32_t off = (uint32_t)(row * 128 + ((c16 ^ (row & 7)) * 16));
            cp_async16(st + off, gAk + (size_t)row * H_DIM + c16 * 8);
        }
        #pragma unroll
        for (int i = 0; i < 8; i++) {
            int chunk = i * THREADS + tid;   // 0..2047
            int row = chunk >> 3;            // 0..255
            int c16 = chunk & 7;
            uint32_t off = (uint32_t)(row * 128 + ((c16 ^ (row & 7)) * 16));
            cp_async16(st + A_BYTES + off, gBk + (size_t)row * H_DIM + c16 * 8);
        }
        asm volatile("cp.async.commit_group;");
    };

    issue_tile(0);

    // f16x2 accumulators: warp tile 64x64 -> 4 mi x 8 ni x 2 regs = 64 regs
    uint32_t c[4][8][2];
    #pragma unroll
    for (int mi = 0; mi < 4; mi++)
        #pragma unroll
        for (int ni = 0; ni < 8; ni++) { c[mi][ni][0] = 0u; c[mi][ni][1] = 0u; }

    // ---- hoisted fragment addressing ----
    const int a_row = warp_m * 64 + (lane & 15);
    const int a_r7 = a_row & 7;
    const int a_kl = lane >> 4;
    uint32_t a_off[4];
    #pragma unroll
    for (int mi = 0; mi < 4; mi++)
        a_off[mi] = (uint32_t)((a_row + mi * 16) * 128 + ((a_kl ^ (a_r7 & 1)) << 4));
    const uint32_t a_xb = (uint32_t)((a_r7 & 6) << 4);

    const int b_row = warp_n * 64 + (lane & 7) + ((lane >> 4) << 3);
    const int b_r7 = b_row & 7;
    const int b_kl = (lane >> 3) & 1;
    uint32_t b_off[4];
    #pragma unroll
    for (int p = 0; p < 4; p++)
        b_off[p] = (uint32_t)(A_BYTES + (b_row + p * 16) * 128 + ((b_kl ^ (b_r7 & 1)) << 4));
    const uint32_t b_xb = (uint32_t)((b_r7 & 6) << 4);

    for (int kt = 0; kt < NK; kt++) {
        asm volatile("cp.async.wait_group 0;");
        __syncthreads();
        if (kt + 1 < NK) issue_tile(kt + 1);   // overlaps compute of kt

        const uint32_t stBase = sbase + (kt & 1) * STAGE_BYTES;

        #pragma unroll
        for (int ks = 0; ks < 4; ks++) {   // 4 x k16 per tile
            const uint32_t axr = ((uint32_t)(ks << 5)) ^ a_xb;
            const uint32_t bxr = ((uint32_t)(ks << 5)) ^ b_xb;
            uint32_t a[4][4];
            #pragma unroll
            for (int mi = 0; mi < 4; mi++) {
                uint32_t addr = stBase + a_off[mi] + axr;
                asm volatile(
                    "ldmatrix.sync.aligned.m8n8.x4.shared.b16 {%0,%1,%2,%3}, [%4];"
                    : "=r"(a[mi][0]), "=r"(a[mi][1]), "=r"(a[mi][2]), "=r"(a[mi][3])
                    : "r"(addr));
            }
            uint32_t b[4][4];
            #pragma unroll
            for (int p = 0; p < 4; p++) {
                uint32_t addr = stBase + b_off[p] + bxr;
                asm volatile(
                    "ldmatrix.sync.aligned.m8n8.x4.shared.b16 {%0,%1,%2,%3}, [%4];"
                    : "=r"(b[p][0]), "=r"(b[p][1]), "=r"(b[p][2]), "=r"(b[p][3])
                    : "r"(addr));
            }
            #pragma unroll
            for (int mi = 0; mi < 4; mi++) {
                #pragma unroll
                for (int ni = 0; ni < 8; ni++) {
                    int p = ni >> 1;
                    int o = (ni & 1) * 2;
                    asm volatile(
                        "mma.sync.aligned.m16n8k16.row.col.f16.f16.f16.f16 "
                        "{%0,%1}, {%2,%3,%4,%5}, {%6,%7}, {%0,%1};"
                        : "+r"(c[mi][ni][0]), "+r"(c[mi][ni][1])
                        : "r"(a[mi][0]), "r"(a[mi][1]), "r"(a[mi][2]), "r"(a[mi][3]),
                          "r"(b[p][o]), "r"(b[p][o + 1]));
                }
            }
        }
    }

    // ---- epilogue: (logit - y)^2 ----
    const int gr = lane >> 2;
    const int gc = (lane & 3) * 2;
    float acc = 0.0f;
    #pragma unroll
    for (int mi = 0; mi < 4; mi++) {
        int gn0 = n_blk + warp_m * 64 + mi * 16 + gr;
        const float* y0 = y + (size_t)gn0 * V_DIM + v_blk;
        const float* y8 = y0 + (size_t)8 * V_DIM;
        #pragma unroll
        for (int ni = 0; ni < 8; ni++) {
            int col = warp_n * 64 + ni * 8 + gc;
            float2 y01 = *(const float2*)(y0 + col);
            float2 y23 = *(const float2*)(y8 + col);
            float2 c01 = __half22float2(*(__half2*)&c[mi][ni][0]);
            float2 c23 = __half22float2(*(__half2*)&c[mi][ni][1]);
            float d0 = c01.x - y01.x;
            float d1 = c01.y - y01.y;
            float d2 = c23.x - y23.x;
            float d3 = c23.y - y23.y;
            acc += d0 * d0 + d1 * d1 + d2 * d2 + d3 * d3;
        }
    }
    #pragma unroll
    for (int off = 16; off; off >>= 1)
        acc += __shfl_xor_sync(0xFFFFFFFFu, acc, off);
    if (lane == 0) red[warp] = acc;
    __syncthreads();
    if (warp == 0) {
        float sv = (lane < 8) ? red[lane] : 0.0f;
        #pragma unroll
        for (int off = 4; off; off >>= 1)
            sv += __shfl_xor_sync(0xFFFFFFFFu, sv, off);
        if (lane == 0) {
            atomicAdd(&g_acc, (double)sv);
            __threadfence();
            unsigned done = atomicAdd(&g_count, 1u);
            if (done == NUM_CTAS - 1) {
                double total = atomicAdd(&g_acc, 0.0);   // ordered read
                out[0] = (float)(total / ((double)N_DIM * (double)V_DIM));
                g_count = 0;   // reset for next graph replay
            }
        }
    }
}

// ============================================================
extern "C" void kernel_launch(void* const* d_in, const int* in_sizes, int n_in,
                              void* d_out, int out_size) {
    (void)in_sizes; (void)n_in; (void)out_size;
    const float* x = (const float*)d_in[0];   // [N, H]
    const float* y = (const float*)d_in[1];   // [N, V]
    const float* W = (const float*)d_in[2];   // [V, H]
    float* out = (float*)d_out;

    static bool attr_set = false;
    if (!attr_set) {
        cudaFuncSetAttribute(gemm_mse_kernel,
                             cudaFuncAttributeMaxDynamicSharedMemorySize,
                             SMEM_BYTES);
        attr_set = true;
    }

    convert_kernel<<<2048, 256>>>(x, W);

    dim3 grid(N_DIM / BM, V_DIM / BN);  // (16, 125): x-fastest -> W stripe L2 reuse
    gemm_mse_kernel<<<grid, THREADS, SMEM_BYTES>>>(y, out);
}